// round 2
// baseline (speedup 1.0000x reference)
#include <cuda_runtime.h>

#define BB 4
#define TT 2048
#define CC 1024
#define HH 16
#define DHH 64
#define M_TOT (BB*TT)   // 8192

// Scratch (static device globals — no allocation in kernel_launch)
__device__ float g_q[BB*HH*TT*DHH];
__device__ float g_k[BB*HH*TT*DHH];
__device__ float g_v[BB*HH*TT*DHH];
__device__ float g_att[BB*TT*CC];

// ---------------- packed f32x2 helpers ----------------
__device__ __forceinline__ unsigned long long pk2(float x, float y) {
    unsigned long long r;
    asm("mov.b64 %0, {%1, %2};" : "=l"(r) : "f"(x), "f"(y));
    return r;
}
__device__ __forceinline__ void upk2(unsigned long long p, float& x, float& y) {
    asm("mov.b64 {%0, %1}, %2;" : "=f"(x), "=f"(y) : "l"(p));
}
__device__ __forceinline__ unsigned long long ffma2(unsigned long long a, unsigned long long b, unsigned long long c) {
    unsigned long long d;
    asm("fma.rn.f32x2 %0, %1, %2, %3;" : "=l"(d) : "l"(a), "l"(b), "l"(c));
    return d;
}
__device__ __forceinline__ unsigned long long fmul2(unsigned long long a, unsigned long long b) {
    unsigned long long d;
    asm("mul.rn.f32x2 %0, %1, %2;" : "=l"(d) : "l"(a), "l"(b));
    return d;
}

// ============================================================
// Kernel 1: fused QKV projection.
// Grid (64, 24): x = M-tile (128 rows of x), y: tensor(3) x n-tile(8, 128 cols)
// Block 256 threads, 128x128 tile, per-thread 8x8 (as 2x2 of 4x4 quads).
// ============================================================
__global__ void __launch_bounds__(256) qkv_kernel(
    const float* __restrict__ x,
    const float* __restrict__ Wq,
    const float* __restrict__ Wk,
    const float* __restrict__ Wv)
{
    __shared__ __align__(16) float as[16][132];
    __shared__ __align__(16) float bs[16][132];

    const int tid = threadIdx.x;
    const int tx = tid & 15;
    const int ty = tid >> 4;

    const int m0  = blockIdx.x * 128;
    const int sel = blockIdx.y >> 3;            // 0=q, 1=k, 2=v
    const int n0  = (blockIdx.y & 7) * 128;     // within C=1024 (2 heads)

    const float* W = (sel == 0) ? Wq : (sel == 1 ? Wk : Wv);
    float* out     = (sel == 0) ? g_q : (sel == 1 ? g_k : g_v);

    unsigned long long acc[8][4];
#pragma unroll
    for (int i = 0; i < 8; i++)
#pragma unroll
        for (int jp = 0; jp < 4; jp++) acc[i][jp] = 0ull;

    const int a_m  = tid >> 2;           // 0..63
    const int a_k4 = (tid & 3) << 2;     // 0,4,8,12
    const int b_k  = tid >> 4;           // 0..15
    const int b_n4 = (tid & 15) << 2;    // 0..60

    for (int k0 = 0; k0 < CC; k0 += 16) {
        // A tile: as[k][m]  (x is [m, C])
#pragma unroll
        for (int r = 0; r < 2; r++) {
            int ml = a_m + r * 64;
            float4 xa = *reinterpret_cast<const float4*>(&x[(size_t)(m0 + ml) * CC + k0 + a_k4]);
            as[a_k4 + 0][ml] = xa.x;
            as[a_k4 + 1][ml] = xa.y;
            as[a_k4 + 2][ml] = xa.z;
            as[a_k4 + 3][ml] = xa.w;
        }
        // B tile: bs[k][n]   W layout [H, C, DH]; col n -> head=(n0+n)>>6, d=(n0+n)&63
#pragma unroll
        for (int half = 0; half < 2; half++) {
            int head = (n0 >> 6) + half;
            float4 wb = *reinterpret_cast<const float4*>(
                &W[(size_t)head * CC * DHH + (size_t)(k0 + b_k) * DHH + b_n4]);
            *reinterpret_cast<float4*>(&bs[b_k][half * 64 + b_n4]) = wb;
        }
        __syncthreads();

#pragma unroll
        for (int kk = 0; kk < 16; kk++) {
            float4 a0 = *reinterpret_cast<const float4*>(&as[kk][ty * 4]);
            float4 a1 = *reinterpret_cast<const float4*>(&as[kk][64 + ty * 4]);
            ulonglong2 b0 = *reinterpret_cast<const ulonglong2*>(&bs[kk][tx * 4]);
            ulonglong2 b1 = *reinterpret_cast<const ulonglong2*>(&bs[kk][64 + tx * 4]);
            unsigned long long ap[8];
            ap[0] = pk2(a0.x, a0.x); ap[1] = pk2(a0.y, a0.y);
            ap[2] = pk2(a0.z, a0.z); ap[3] = pk2(a0.w, a0.w);
            ap[4] = pk2(a1.x, a1.x); ap[5] = pk2(a1.y, a1.y);
            ap[6] = pk2(a1.z, a1.z); ap[7] = pk2(a1.w, a1.w);
#pragma unroll
            for (int i = 0; i < 8; i++) {
                acc[i][0] = ffma2(ap[i], b0.x, acc[i][0]);
                acc[i][1] = ffma2(ap[i], b0.y, acc[i][1]);
                acc[i][2] = ffma2(ap[i], b1.x, acc[i][2]);
                acc[i][3] = ffma2(ap[i], b1.y, acc[i][3]);
            }
        }
        __syncthreads();
    }

    // Epilogue: write q/k/v in [B,H,T,DH]
#pragma unroll
    for (int i = 0; i < 8; i++) {
        int m = m0 + ((i < 4) ? (ty * 4 + i) : (64 + ty * 4 + i - 4));
        int bb = m / TT, trow = m % TT;
#pragma unroll
        for (int half = 0; half < 2; half++) {
            float f0, f1, f2, f3;
            upk2(acc[i][half * 2 + 0], f0, f1);
            upk2(acc[i][half * 2 + 1], f2, f3);
            int n = n0 + half * 64 + tx * 4;
            int head = n >> 6;
            int d = n & 63;
            float4 o4 = make_float4(f0, f1, f2, f3);
            *reinterpret_cast<float4*>(
                &out[((size_t)(bb * HH + head) * TT + trow) * DHH + d]) = o4;
        }
    }
}

// ============================================================
// Kernel 2: causal flash attention, fp32.
// Grid (T/64, B*H), 256 threads. BR=BC=64, per-thread 4x4 of S/P/O.
// Dynamic smem: qs(16K) + ks(16K, xor-swizzled) + vs(16K) + ps2(32K u64 pairs)
// ============================================================
#define ATTN_SMEM (3 * 64 * 64 * 4 + 64 * 64 * 8)

__global__ void __launch_bounds__(256) attn_kernel()
{
    extern __shared__ __align__(16) char smem_raw[];
    float* qs = reinterpret_cast<float*>(smem_raw);
    float* ks = qs + 64 * 64;
    float* vs = ks + 64 * 64;
    unsigned long long* ps2 = reinterpret_cast<unsigned long long*>(vs + 64 * 64);

    const int tid = threadIdx.x;
    const int tx = tid & 15;
    const int ty = tid >> 4;
    const int qt = blockIdx.x;
    const int bh = blockIdx.y;
    const size_t base = (size_t)bh * TT * DHH;

    // Load Q tile, fold in softmax scale 1/sqrt(DH)=0.125
    for (int idx = tid; idx < 64 * 16; idx += 256) {
        int r = idx >> 4, d4 = (idx & 15) << 2;
        float4 qv = *reinterpret_cast<const float4*>(&g_q[base + (size_t)(qt * 64 + r) * DHH + d4]);
        qv.x *= 0.125f; qv.y *= 0.125f; qv.z *= 0.125f; qv.w *= 0.125f;
        *reinterpret_cast<float4*>(&qs[r * 64 + d4]) = qv;
    }

    unsigned long long o2[4][2];
    float mrow[4], lrow[4];
#pragma unroll
    for (int i = 0; i < 4; i++) {
        o2[i][0] = 0ull; o2[i][1] = 0ull;
        mrow[i] = -1e30f; lrow[i] = 0.0f;
    }

    for (int kt = 0; kt <= qt; kt++) {
        __syncthreads();   // protect ks/vs/ps2 reuse
        for (int idx = tid; idx < 64 * 16; idx += 256) {
            int r = idx >> 4, d4 = idx & 15;
            float4 kv = *reinterpret_cast<const float4*>(
                &g_k[base + (size_t)(kt * 64 + r) * DHH + (d4 << 2)]);
            int sd4 = d4 ^ ((r >> 2) & 7);   // xor swizzle: conflict-free k-frag reads
            *reinterpret_cast<float4*>(&ks[r * 64 + (sd4 << 2)]) = kv;
            float4 vv = *reinterpret_cast<const float4*>(
                &g_v[base + (size_t)(kt * 64 + r) * DHH + (d4 << 2)]);
            *reinterpret_cast<float4*>(&vs[r * 64 + (d4 << 2)]) = vv;
        }
        __syncthreads();

        // S = (Q*scale) K^T, pairs accumulated along d
        unsigned long long s2[4][4];
#pragma unroll
        for (int i = 0; i < 4; i++)
#pragma unroll
            for (int j = 0; j < 4; j++) s2[i][j] = 0ull;

#pragma unroll 4
        for (int d4 = 0; d4 < 16; d4++) {
            unsigned long long qa[4], qb[4], ka[4], kb[4];
#pragma unroll
            for (int i = 0; i < 4; i++) {
                ulonglong2 qp = *reinterpret_cast<const ulonglong2*>(
                    &qs[(ty * 4 + i) * 64 + (d4 << 2)]);
                qa[i] = qp.x; qb[i] = qp.y;
            }
#pragma unroll
            for (int j = 0; j < 4; j++) {
                int c = tx * 4 + j;
                int sd4 = d4 ^ ((c >> 2) & 7);
                ulonglong2 kp = *reinterpret_cast<const ulonglong2*>(
                    &ks[c * 64 + (sd4 << 2)]);
                ka[j] = kp.x; kb[j] = kp.y;
            }
#pragma unroll
            for (int i = 0; i < 4; i++)
#pragma unroll
                for (int j = 0; j < 4; j++) {
                    s2[i][j] = ffma2(qa[i], ka[j], s2[i][j]);
                    s2[i][j] = ffma2(qb[i], kb[j], s2[i][j]);
                }
        }

        // Online softmax
        const bool diag = (kt == qt);
#pragma unroll
        for (int i = 0; i < 4; i++) {
            float sv[4];
            float mloc = -1e30f;
#pragma unroll
            for (int j = 0; j < 4; j++) {
                float lo, hi;
                upk2(s2[i][j], lo, hi);
                float s = lo + hi;
                if (diag && (tx * 4 + j > ty * 4 + i)) s = -1e30f;
                sv[j] = s;
                mloc = fmaxf(mloc, s);
            }
#pragma unroll
            for (int w = 1; w < 16; w <<= 1)
                mloc = fmaxf(mloc, __shfl_xor_sync(0xffffffffu, mloc, w));
            float mnew = fmaxf(mrow[i], mloc);
            float fac = __expf(mrow[i] - mnew);
            mrow[i] = mnew;
            float rsum = 0.0f;
            float pv[4];
#pragma unroll
            for (int j = 0; j < 4; j++) {
                pv[j] = __expf(sv[j] - mnew);
                rsum += pv[j];
            }
#pragma unroll
            for (int w = 1; w < 16; w <<= 1)
                rsum += __shfl_xor_sync(0xffffffffu, rsum, w);
            lrow[i] = lrow[i] * fac + rsum;
            unsigned long long f2 = pk2(fac, fac);
            o2[i][0] = fmul2(o2[i][0], f2);
            o2[i][1] = fmul2(o2[i][1], f2);
#pragma unroll
            for (int j = 0; j < 4; j++)
                ps2[(ty * 4 + i) * 64 + tx * 4 + j] = pk2(pv[j], pv[j]);
        }
        __syncthreads();

        // O += P V   (p pre-duplicated pairs -> zero packing)
#pragma unroll 8
        for (int j = 0; j < 64; j++) {
            ulonglong2 vp = *reinterpret_cast<const ulonglong2*>(&vs[j * 64 + tx * 4]);
#pragma unroll
            for (int i = 0; i < 4; i++) {
                unsigned long long pp = ps2[(ty * 4 + i) * 64 + j];
                o2[i][0] = ffma2(pp, vp.x, o2[i][0]);
                o2[i][1] = ffma2(pp, vp.y, o2[i][1]);
            }
        }
    }

    // Finalize: O / l, write concat-head layout [B, T, C]
    const int bb = bh >> 4, hh = bh & 15;
#pragma unroll
    for (int i = 0; i < 4; i++) {
        float inv = 1.0f / lrow[i];
        float f0, f1, f2, f3;
        upk2(o2[i][0], f0, f1);
        upk2(o2[i][1], f2, f3);
        float4 o4 = make_float4(f0 * inv, f1 * inv, f2 * inv, f3 * inv);
        int trow = qt * 64 + ty * 4 + i;
        *reinterpret_cast<float4*>(
            &g_att[(size_t)(bb * TT + trow) * CC + hh * DHH + tx * 4]) = o4;
    }
}

// ============================================================
// Kernel 3: output projection  out = att @ Wo^T + bo
// Grid (64, 8), same 128x128 tiling as kernel 1.
// ============================================================
__global__ void __launch_bounds__(256) proj_kernel(
    const float* __restrict__ Wo,
    const float* __restrict__ bo,
    float* __restrict__ out)
{
    __shared__ __align__(16) float as[16][132];
    __shared__ __align__(16) float bs[16][132];

    const int tid = threadIdx.x;
    const int tx = tid & 15;
    const int ty = tid >> 4;
    const int m0 = blockIdx.x * 128;
    const int n0 = blockIdx.y * 128;

    unsigned long long acc[8][4];
#pragma unroll
    for (int i = 0; i < 8; i++)
#pragma unroll
        for (int jp = 0; jp < 4; jp++) acc[i][jp] = 0ull;

    const int a_m  = tid >> 2;
    const int a_k4 = (tid & 3) << 2;

    for (int k0 = 0; k0 < CC; k0 += 16) {
#pragma unroll
        for (int r = 0; r < 2; r++) {
            int l = a_m + r * 64;
            float4 xa = *reinterpret_cast<const float4*>(
                &g_att[(size_t)(m0 + l) * CC + k0 + a_k4]);
            as[a_k4 + 0][l] = xa.x; as[a_k4 + 1][l] = xa.y;
            as[a_k4 + 2][l] = xa.z; as[a_k4 + 3][l] = xa.w;
            // Wo is [co, ci]; need bs[k][n] = Wo[n0+n][k0+k] -> transpose on store
            float4 wv = *reinterpret_cast<const float4*>(
                &Wo[(size_t)(n0 + l) * CC + k0 + a_k4]);
            bs[a_k4 + 0][l] = wv.x; bs[a_k4 + 1][l] = wv.y;
            bs[a_k4 + 2][l] = wv.z; bs[a_k4 + 3][l] = wv.w;
        }
        __syncthreads();

#pragma unroll
        for (int kk = 0; kk < 16; kk++) {
            float4 a0 = *reinterpret_cast<const float4*>(&as[kk][ty * 4]);
            float4 a1 = *reinterpret_cast<const float4*>(&as[kk][64 + ty * 4]);
            ulonglong2 b0 = *reinterpret_cast<const ulonglong2*>(&bs[kk][tx * 4]);
            ulonglong2 b1 = *reinterpret_cast<const ulonglong2*>(&bs[kk][64 + tx * 4]);
            unsigned long long ap[8];
            ap[0] = pk2(a0.x, a0.x); ap[1] = pk2(a0.y, a0.y);
            ap[2] = pk2(a0.z, a0.z); ap[3] = pk2(a0.w, a0.w);
            ap[4] = pk2(a1.x, a1.x); ap[5] = pk2(a1.y, a1.y);
            ap[6] = pk2(a1.z, a1.z); ap[7] = pk2(a1.w, a1.w);
#pragma unroll
            for (int i = 0; i < 8; i++) {
                acc[i][0] = ffma2(ap[i], b0.x, acc[i][0]);
                acc[i][1] = ffma2(ap[i], b0.y, acc[i][1]);
                acc[i][2] = ffma2(ap[i], b1.x, acc[i][2]);
                acc[i][3] = ffma2(ap[i], b1.y, acc[i][3]);
            }
        }
        __syncthreads();
    }

    float4 bo0 = *reinterpret_cast<const float4*>(&bo[n0 + tx * 4]);
    float4 bo1 = *reinterpret_cast<const float4*>(&bo[n0 + 64 + tx * 4]);
#pragma unroll
    for (int i = 0; i < 8; i++) {
        int m = m0 + ((i < 4) ? (ty * 4 + i) : (64 + ty * 4 + i - 4));
#pragma unroll
        for (int half = 0; half < 2; half++) {
            float f0, f1, f2, f3;
            upk2(acc[i][half * 2 + 0], f0, f1);
            upk2(acc[i][half * 2 + 1], f2, f3);
            float4 bv = half ? bo1 : bo0;
            float4 o4 = make_float4(f0 + bv.x, f1 + bv.y, f2 + bv.z, f3 + bv.w);
            *reinterpret_cast<float4*>(&out[(size_t)m * CC + n0 + half * 64 + tx * 4]) = o4;
        }
    }
}

// ============================================================
extern "C" void kernel_launch(void* const* d_in, const int* in_sizes, int n_in,
                              void* d_out, int out_size)
{
    const float* x  = (const float*)d_in[0];
    const float* Wq = (const float*)d_in[1];
    const float* Wk = (const float*)d_in[2];
    const float* Wv = (const float*)d_in[3];
    const float* Wo = (const float*)d_in[4];
    const float* bo = (const float*)d_in[5];
    float* out = (float*)d_out;

    cudaFuncSetAttribute(attn_kernel, cudaFuncAttributeMaxDynamicSharedMemorySize, ATTN_SMEM);

    qkv_kernel<<<dim3(M_TOT / 128, 24), 256>>>(x, Wq, Wk, Wv);
    attn_kernel<<<dim3(TT / 64, BB * HH), 256, ATTN_SMEM>>>();
    proj_kernel<<<dim3(M_TOT / 128, 8), 256>>>(Wo, bo, out);
}

// round 4
// speedup vs baseline: 1.4830x; 1.4830x over previous
#include <cuda_runtime.h>
#include <cstdint>

#define BB 4
#define TT 2048
#define CC 1024
#define HH 16
#define DHH 64
#define M_TOT (BB*TT)   // 8192

// Scratch (static device globals — no allocation in kernel_launch)
__device__ float g_q[BB*HH*TT*DHH];
__device__ float g_k[BB*HH*TT*DHH];
__device__ float g_v[BB*HH*TT*DHH];
__device__ float g_att[BB*TT*CC];
__device__ float g_Wt[3*CC*CC];      // transposed qkv weights: [sel][n=h*64+d][k=c]

// ================= helpers =================
__device__ __forceinline__ float to_tf32(float x) {
    uint32_t u;
    asm("cvt.rna.tf32.f32 %0, %1;" : "=r"(u) : "f"(x));
    return __uint_as_float(u);
}

__device__ __forceinline__ void mma_tf32(float c[4],
                                         uint32_t a0, uint32_t a1, uint32_t a2, uint32_t a3,
                                         uint32_t b0, uint32_t b1) {
    asm volatile(
        "mma.sync.aligned.m16n8k8.row.col.f32.tf32.tf32.f32 "
        "{%0,%1,%2,%3}, {%4,%5,%6,%7}, {%8,%9}, {%0,%1,%2,%3};"
        : "+f"(c[0]), "+f"(c[1]), "+f"(c[2]), "+f"(c[3])
        : "r"(a0), "r"(a1), "r"(a2), "r"(a3), "r"(b0), "r"(b1));
}

// ================= packed f32x2 helpers (attention) =================
__device__ __forceinline__ unsigned long long pk2(float x, float y) {
    unsigned long long r;
    asm("mov.b64 %0, {%1, %2};" : "=l"(r) : "f"(x), "f"(y));
    return r;
}
__device__ __forceinline__ void upk2(unsigned long long p, float& x, float& y) {
    asm("mov.b64 {%0, %1}, %2;" : "=f"(x), "=f"(y) : "l"(p));
}
__device__ __forceinline__ unsigned long long ffma2(unsigned long long a, unsigned long long b, unsigned long long c) {
    unsigned long long d;
    asm("fma.rn.f32x2 %0, %1, %2, %3;" : "=l"(d) : "l"(a), "l"(b), "l"(c));
    return d;
}
__device__ __forceinline__ unsigned long long fmul2(unsigned long long a, unsigned long long b) {
    unsigned long long d;
    asm("mul.rn.f32x2 %0, %1, %2;" : "=l"(d) : "l"(a), "l"(b));
    return d;
}

// ============================================================
// Kernel 0: weight transpose  g_Wt[sel][n=h*64+d][k=c] = W_sel[h][c][d]
// grid (32, 32, 3)  block (32, 8)
// ============================================================
__global__ void __launch_bounds__(256) wt_kernel(
    const float* __restrict__ Wq, const float* __restrict__ Wk, const float* __restrict__ Wv)
{
    __shared__ float t[32][33];
    const float* W = (blockIdx.z == 0) ? Wq : (blockIdx.z == 1 ? Wk : Wv);
    float* out = g_Wt + (size_t)blockIdx.z * CC * CC;
    const int head = blockIdx.y >> 1;
    const int d0 = (blockIdx.y & 1) * 32;
    const int k0 = blockIdx.x * 32;
    const int tx = threadIdx.x, ty = threadIdx.y;
#pragma unroll
    for (int j = 0; j < 4; j++) {
        int k = k0 + ty + j * 8;
        t[ty + j * 8][tx] = W[((size_t)head * CC + k) * DHH + d0 + tx];
    }
    __syncthreads();
#pragma unroll
    for (int j = 0; j < 4; j++) {
        int n = head * 64 + d0 + ty + j * 8;
        out[(size_t)n * CC + k0 + tx] = t[tx][ty + j * 8];
    }
}

// ============================================================
// mma.sync tf32 GEMM, 128x128 CTA tile, 8 warps (2x4), warp tile 64x32.
// K staged 32 at a time, double-buffered smem + register prefetch.
// MODE 0: qkv (A=x, B=g_Wt[sel], out=g_q/g_k/g_v in [B,H,T,DH])
// MODE 1: proj (A=g_att, B=Wo [N,K] row-major, out=final +bias)
// ============================================================
#define KT 32
#define NSTAGE (CC / KT)        // 32
#define ASTR 36                 // padded k-stride (floats): banks (4g+t)%32 distinct
#define TILE_F (128 * ASTR)     // 4608 floats per tile
#define GEMM_SMEM (2 * 2 * TILE_F * 4)   // 73728 bytes

template <int MODE>
__global__ void __launch_bounds__(256) gemm_mma(
    const float* __restrict__ Amat, const float* __restrict__ Bmat,
    const float* __restrict__ bias, float* __restrict__ outp)
{
    extern __shared__ __align__(16) float smem[];
    // layout: [buf][A/B][TILE_F]
    const int tid = threadIdx.x;
    const int lane = tid & 31, wid = tid >> 5;
    const int g = lane >> 2;       // group id 0..7
    const int tg = lane & 3;       // thread in group 0..3
    const int warp_m = (wid & 1) * 64;
    const int warp_n = (wid >> 1) * 32;
    const int m0 = blockIdx.x * 128;

    int n0;
    const float* Ap;
    const float* Bp;
    float* op;
    if (MODE == 0) {
        const int sel = blockIdx.y >> 3;
        n0 = (blockIdx.y & 7) * 128;
        Ap = Amat;
        Bp = g_Wt + (size_t)sel * CC * CC;
        op = (sel == 0) ? g_q : (sel == 1 ? g_k : g_v);
    } else {
        n0 = blockIdx.y * 128;
        Ap = g_att;
        Bp = Bmat;
        op = outp;
    }

    float acc[4][4][4];
#pragma unroll
    for (int im = 0; im < 4; im++)
#pragma unroll
        for (int in = 0; in < 4; in++)
#pragma unroll
            for (int c = 0; c < 4; c++) acc[im][in][c] = 0.0f;

    // loader mapping: idx = tid + j*256; r = idx>>3 (0..127), c4 = (idx&7)*4
    float4 pa[4], pb[4];

    // ---- prologue: load stage 0 ----
#pragma unroll
    for (int j = 0; j < 4; j++) {
        int idx = tid + j * 256;
        int r = idx >> 3, c4 = (idx & 7) << 2;
        pa[j] = *reinterpret_cast<const float4*>(&Ap[(size_t)(m0 + r) * CC + c4]);
        pb[j] = *reinterpret_cast<const float4*>(&Bp[(size_t)(n0 + r) * CC + c4]);
    }
    {
        float* sA = smem;            // buf0 A
        float* sB = smem + TILE_F;   // buf0 B
#pragma unroll
        for (int j = 0; j < 4; j++) {
            int idx = tid + j * 256;
            int r = idx >> 3, c4 = (idx & 7) << 2;
            float4 v = pa[j];
            sA[r * ASTR + c4 + 0] = to_tf32(v.x); sA[r * ASTR + c4 + 1] = to_tf32(v.y);
            sA[r * ASTR + c4 + 2] = to_tf32(v.z); sA[r * ASTR + c4 + 3] = to_tf32(v.w);
            float4 w = pb[j];
            sB[r * ASTR + c4 + 0] = to_tf32(w.x); sB[r * ASTR + c4 + 1] = to_tf32(w.y);
            sB[r * ASTR + c4 + 2] = to_tf32(w.z); sB[r * ASTR + c4 + 3] = to_tf32(w.w);
        }
    }
    __syncthreads();

    for (int s = 0; s < NSTAGE; s++) {
        // prefetch next stage into registers
        if (s + 1 < NSTAGE) {
            const int k0 = (s + 1) * KT;
#pragma unroll
            for (int j = 0; j < 4; j++) {
                int idx = tid + j * 256;
                int r = idx >> 3, c4 = (idx & 7) << 2;
                pa[j] = *reinterpret_cast<const float4*>(&Ap[(size_t)(m0 + r) * CC + k0 + c4]);
                pb[j] = *reinterpret_cast<const float4*>(&Bp[(size_t)(n0 + r) * CC + k0 + c4]);
            }
        }

        // compute from buf s&1
        const float* sA = smem + (s & 1) * 2 * TILE_F;
        const float* sB = sA + TILE_F;
#pragma unroll
        for (int k8 = 0; k8 < 4; k8++) {
            const int kk = k8 * 8 + tg;
            uint32_t bf[4][2];
#pragma unroll
            for (int in = 0; in < 4; in++) {
                int n = warp_n + in * 8 + g;
                bf[in][0] = __float_as_uint(sB[n * ASTR + kk]);
                bf[in][1] = __float_as_uint(sB[n * ASTR + kk + 4]);
            }
#pragma unroll
            for (int im = 0; im < 4; im++) {
                int m = warp_m + im * 16 + g;
                uint32_t a0 = __float_as_uint(sA[m * ASTR + kk]);
                uint32_t a1 = __float_as_uint(sA[(m + 8) * ASTR + kk]);
                uint32_t a2 = __float_as_uint(sA[m * ASTR + kk + 4]);
                uint32_t a3 = __float_as_uint(sA[(m + 8) * ASTR + kk + 4]);
#pragma unroll
                for (int in = 0; in < 4; in++)
                    mma_tf32(acc[im][in], a0, a1, a2, a3, bf[in][0], bf[in][1]);
            }
        }

        if (s + 1 < NSTAGE) {
            __syncthreads();   // everyone done reading buf (s+1)&1 from stage s-1
            float* dA = smem + ((s + 1) & 1) * 2 * TILE_F;
            float* dB = dA + TILE_F;
#pragma unroll
            for (int j = 0; j < 4; j++) {
                int idx = tid + j * 256;
                int r = idx >> 3, c4 = (idx & 7) << 2;
                float4 v = pa[j];
                dA[r * ASTR + c4 + 0] = to_tf32(v.x); dA[r * ASTR + c4 + 1] = to_tf32(v.y);
                dA[r * ASTR + c4 + 2] = to_tf32(v.z); dA[r * ASTR + c4 + 3] = to_tf32(v.w);
                float4 w = pb[j];
                dB[r * ASTR + c4 + 0] = to_tf32(w.x); dB[r * ASTR + c4 + 1] = to_tf32(w.y);
                dB[r * ASTR + c4 + 2] = to_tf32(w.z); dB[r * ASTR + c4 + 3] = to_tf32(w.w);
            }
            __syncthreads();
        }
    }

    // ---- epilogue ----
#pragma unroll
    for (int im = 0; im < 4; im++) {
#pragma unroll
        for (int in = 0; in < 4; in++) {
            int row0 = m0 + warp_m + im * 16 + g;
            int col = n0 + warp_n + in * 8 + tg * 2;
            if (MODE == 0) {
                int head = col >> 6, d = col & 63;
#pragma unroll
                for (int h = 0; h < 2; h++) {
                    int m = row0 + h * 8;
                    int b = m >> 11, t = m & 2047;
                    float2 v = make_float2(acc[im][in][h * 2], acc[im][in][h * 2 + 1]);
                    *reinterpret_cast<float2*>(
                        &op[((size_t)(b * HH + head) * TT + t) * DHH + d]) = v;
                }
            } else {
                float b0 = bias[col], b1 = bias[col + 1];
#pragma unroll
                for (int h = 0; h < 2; h++) {
                    int m = row0 + h * 8;
                    float2 v = make_float2(acc[im][in][h * 2] + b0, acc[im][in][h * 2 + 1] + b1);
                    *reinterpret_cast<float2*>(&op[(size_t)m * CC + col]) = v;
                }
            }
        }
    }
}

// ============================================================
// Kernel 2: causal flash attention, fp32 SIMT (verified R2)
// ============================================================
#define ATTN_SMEM (3 * 64 * 64 * 4 + 64 * 64 * 8)

__global__ void __launch_bounds__(256) attn_kernel()
{
    extern __shared__ __align__(16) char smem_raw[];
    float* qs = reinterpret_cast<float*>(smem_raw);
    float* ks = qs + 64 * 64;
    float* vs = ks + 64 * 64;
    unsigned long long* ps2 = reinterpret_cast<unsigned long long*>(vs + 64 * 64);

    const int tid = threadIdx.x;
    const int tx = tid & 15;
    const int ty = tid >> 4;
    const int qt = blockIdx.x;
    const int bh = blockIdx.y;
    const size_t base = (size_t)bh * TT * DHH;

    for (int idx = tid; idx < 64 * 16; idx += 256) {
        int r = idx >> 4, d4 = (idx & 15) << 2;
        float4 qv = *reinterpret_cast<const float4*>(&g_q[base + (size_t)(qt * 64 + r) * DHH + d4]);
        qv.x *= 0.125f; qv.y *= 0.125f; qv.z *= 0.125f; qv.w *= 0.125f;
        *reinterpret_cast<float4*>(&qs[r * 64 + d4]) = qv;
    }

    unsigned long long o2[4][2];
    float mrow[4], lrow[4];
#pragma unroll
    for (int i = 0; i < 4; i++) {
        o2[i][0] = 0ull; o2[i][1] = 0ull;
        mrow[i] = -1e30f; lrow[i] = 0.0f;
    }

    for (int kt = 0; kt <= qt; kt++) {
        __syncthreads();
        for (int idx = tid; idx < 64 * 16; idx += 256) {
            int r = idx >> 4, d4 = idx & 15;
            float4 kv = *reinterpret_cast<const float4*>(
                &g_k[base + (size_t)(kt * 64 + r) * DHH + (d4 << 2)]);
            int sd4 = d4 ^ ((r >> 2) & 7);
            *reinterpret_cast<float4*>(&ks[r * 64 + (sd4 << 2)]) = kv;
            float4 vv = *reinterpret_cast<const float4*>(
                &g_v[base + (size_t)(kt * 64 + r) * DHH + (d4 << 2)]);
            *reinterpret_cast<float4*>(&vs[r * 64 + (d4 << 2)]) = vv;
        }
        __syncthreads();

        unsigned long long s2[4][4];
#pragma unroll
        for (int i = 0; i < 4; i++)
#pragma unroll
            for (int j = 0; j < 4; j++) s2[i][j] = 0ull;

#pragma unroll 4
        for (int d4 = 0; d4 < 16; d4++) {
            unsigned long long qa[4], qb[4], ka[4], kb[4];
#pragma unroll
            for (int i = 0; i < 4; i++) {
                ulonglong2 qp = *reinterpret_cast<const ulonglong2*>(
                    &qs[(ty * 4 + i) * 64 + (d4 << 2)]);
                qa[i] = qp.x; qb[i] = qp.y;
            }
#pragma unroll
            for (int j = 0; j < 4; j++) {
                int c = tx * 4 + j;
                int sd4 = d4 ^ ((c >> 2) & 7);
                ulonglong2 kp = *reinterpret_cast<const ulonglong2*>(
                    &ks[c * 64 + (sd4 << 2)]);
                ka[j] = kp.x; kb[j] = kp.y;
            }
#pragma unroll
            for (int i = 0; i < 4; i++)
#pragma unroll
                for (int j = 0; j < 4; j++) {
                    s2[i][j] = ffma2(qa[i], ka[j], s2[i][j]);
                    s2[i][j] = ffma2(qb[i], kb[j], s2[i][j]);
                }
        }

        const bool diag = (kt == qt);
#pragma unroll
        for (int i = 0; i < 4; i++) {
            float sv[4];
            float mloc = -1e30f;
#pragma unroll
            for (int j = 0; j < 4; j++) {
                float lo, hi;
                upk2(s2[i][j], lo, hi);
                float s = lo + hi;
                if (diag && (tx * 4 + j > ty * 4 + i)) s = -1e30f;
                sv[j] = s;
                mloc = fmaxf(mloc, s);
            }
#pragma unroll
            for (int w = 1; w < 16; w <<= 1)
                mloc = fmaxf(mloc, __shfl_xor_sync(0xffffffffu, mloc, w));
            float mnew = fmaxf(mrow[i], mloc);
            float fac = __expf(mrow[i] - mnew);
            mrow[i] = mnew;
            float rsum = 0.0f;
            float pv[4];
#pragma unroll
            for (int j = 0; j < 4; j++) {
                pv[j] = __expf(sv[j] - mnew);
                rsum += pv[j];
            }
#pragma unroll
            for (int w = 1; w < 16; w <<= 1)
                rsum += __shfl_xor_sync(0xffffffffu, rsum, w);
            lrow[i] = lrow[i] * fac + rsum;
            unsigned long long f2 = pk2(fac, fac);
            o2[i][0] = fmul2(o2[i][0], f2);
            o2[i][1] = fmul2(o2[i][1], f2);
#pragma unroll
            for (int j = 0; j < 4; j++)
                ps2[(ty * 4 + i) * 64 + tx * 4 + j] = pk2(pv[j], pv[j]);
        }
        __syncthreads();

#pragma unroll 8
        for (int j = 0; j < 64; j++) {
            ulonglong2 vp = *reinterpret_cast<const ulonglong2*>(&vs[j * 64 + tx * 4]);
#pragma unroll
            for (int i = 0; i < 4; i++) {
                unsigned long long pp = ps2[(ty * 4 + i) * 64 + j];
                o2[i][0] = ffma2(pp, vp.x, o2[i][0]);
                o2[i][1] = ffma2(pp, vp.y, o2[i][1]);
            }
        }
    }

    const int bb = bh >> 4, hh = bh & 15;
#pragma unroll
    for (int i = 0; i < 4; i++) {
        float inv = 1.0f / lrow[i];
        float f0, f1, f2, f3;
        upk2(o2[i][0], f0, f1);
        upk2(o2[i][1], f2, f3);
        float4 o4 = make_float4(f0 * inv, f1 * inv, f2 * inv, f3 * inv);
        int trow = qt * 64 + ty * 4 + i;
        *reinterpret_cast<float4*>(
            &g_att[(size_t)(bb * TT + trow) * CC + hh * DHH + tx * 4]) = o4;
    }
}

// ============================================================
extern "C" void kernel_launch(void* const* d_in, const int* in_sizes, int n_in,
                              void* d_out, int out_size)
{
    const float* x  = (const float*)d_in[0];
    const float* Wq = (const float*)d_in[1];
    const float* Wk = (const float*)d_in[2];
    const float* Wv = (const float*)d_in[3];
    const float* Wo = (const float*)d_in[4];
    const float* bo = (const float*)d_in[5];
    float* out = (float*)d_out;

    cudaFuncSetAttribute(gemm_mma<0>, cudaFuncAttributeMaxDynamicSharedMemorySize, GEMM_SMEM);
    cudaFuncSetAttribute(gemm_mma<1>, cudaFuncAttributeMaxDynamicSharedMemorySize, GEMM_SMEM);
    cudaFuncSetAttribute(attn_kernel, cudaFuncAttributeMaxDynamicSharedMemorySize, ATTN_SMEM);

    wt_kernel<<<dim3(32, 32, 3), dim3(32, 8)>>>(Wq, Wk, Wv);
    gemm_mma<0><<<dim3(M_TOT / 128, 24), 256, GEMM_SMEM>>>(x, nullptr, nullptr, nullptr);
    attn_kernel<<<dim3(TT / 64, BB * HH), 256, ATTN_SMEM>>>();
    gemm_mma<1><<<dim3(M_TOT / 128, 8), 256, GEMM_SMEM>>>(nullptr, Wo, bo, out);
}

// round 5
// speedup vs baseline: 1.4861x; 1.0021x over previous
#include <cuda_runtime.h>
#include <cstdint>

#define BB 4
#define TT 2048
#define CC 1024
#define HH 16
#define DHH 64
#define M_TOT (BB*TT)   // 8192

// Scratch (static device globals — no allocation in kernel_launch)
__device__ float g_q[BB*HH*TT*DHH];
__device__ float g_k[BB*HH*TT*DHH];
__device__ float g_v[BB*HH*TT*DHH];
__device__ float g_att[BB*TT*CC];
__device__ float g_Wt[3*CC*CC];      // transposed qkv weights: [sel][n=h*64+d][k=c]

// ================= helpers =================
__device__ __forceinline__ float to_tf32(float x) {
    uint32_t u;
    asm("cvt.rna.tf32.f32 %0, %1;" : "=r"(u) : "f"(x));
    return __uint_as_float(u);
}

__device__ __forceinline__ void mma_tf32(float c[4],
                                         uint32_t a0, uint32_t a1, uint32_t a2, uint32_t a3,
                                         uint32_t b0, uint32_t b1) {
    asm volatile(
        "mma.sync.aligned.m16n8k8.row.col.f32.tf32.tf32.f32 "
        "{%0,%1,%2,%3}, {%4,%5,%6,%7}, {%8,%9}, {%0,%1,%2,%3};"
        : "+f"(c[0]), "+f"(c[1]), "+f"(c[2]), "+f"(c[3])
        : "r"(a0), "r"(a1), "r"(a2), "r"(a3), "r"(b0), "r"(b1));
}

// ================= packed f32x2 helpers (attention) =================
__device__ __forceinline__ unsigned long long pk2(float x, float y) {
    unsigned long long r;
    asm("mov.b64 %0, {%1, %2};" : "=l"(r) : "f"(x), "f"(y));
    return r;
}
__device__ __forceinline__ void upk2(unsigned long long p, float& x, float& y) {
    asm("mov.b64 {%0, %1}, %2;" : "=f"(x), "=f"(y) : "l"(p));
}
__device__ __forceinline__ unsigned long long ffma2(unsigned long long a, unsigned long long b, unsigned long long c) {
    unsigned long long d;
    asm("fma.rn.f32x2 %0, %1, %2, %3;" : "=l"(d) : "l"(a), "l"(b), "l"(c));
    return d;
}
__device__ __forceinline__ unsigned long long fmul2(unsigned long long a, unsigned long long b) {
    unsigned long long d;
    asm("mul.rn.f32x2 %0, %1, %2;" : "=l"(d) : "l"(a), "l"(b));
    return d;
}

// ============================================================
// Kernel 0: weight transpose  g_Wt[sel][n=h*64+d][k=c] = W_sel[h][c][d]
// grid (32, 32, 3)  block (32, 8)
// ============================================================
__global__ void __launch_bounds__(256) wt_kernel(
    const float* __restrict__ Wq, const float* __restrict__ Wk, const float* __restrict__ Wv)
{
    __shared__ float t[32][33];
    const float* W = (blockIdx.z == 0) ? Wq : (blockIdx.z == 1 ? Wk : Wv);
    float* out = g_Wt + (size_t)blockIdx.z * CC * CC;
    const int head = blockIdx.y >> 1;
    const int d0 = (blockIdx.y & 1) * 32;
    const int k0 = blockIdx.x * 32;
    const int tx = threadIdx.x, ty = threadIdx.y;
#pragma unroll
    for (int j = 0; j < 4; j++) {
        int k = k0 + ty + j * 8;
        t[ty + j * 8][tx] = W[((size_t)head * CC + k) * DHH + d0 + tx];
    }
    __syncthreads();
#pragma unroll
    for (int j = 0; j < 4; j++) {
        int n = head * 64 + d0 + ty + j * 8;
        out[(size_t)n * CC + k0 + tx] = t[tx][ty + j * 8];
    }
}

// ============================================================
// mma.sync tf32 GEMM, 128x128 CTA tile, 8 warps (2x4), warp tile 64x32.
// K staged 32 at a time, double-buffered smem + register prefetch.
// MODE 0: qkv (A=x, B=g_Wt[sel], out=g_q/g_k/g_v in [B,H,T,DH])
// MODE 1: proj (A=g_att, B=Wo [N,K] row-major, out=final +bias)
// ============================================================
#define KT 32
#define NSTAGE (CC / KT)        // 32
#define ASTR 36                 // padded k-stride (floats): banks (4g+t)%32 distinct
#define TILE_F (128 * ASTR)     // 4608 floats per tile
#define GEMM_SMEM (2 * 2 * TILE_F * 4)   // 73728 bytes

template <int MODE>
__global__ void __launch_bounds__(256) gemm_mma(
    const float* __restrict__ Amat, const float* __restrict__ Bmat,
    const float* __restrict__ bias, float* __restrict__ outp)
{
    extern __shared__ __align__(16) float smem[];
    // layout: [buf][A/B][TILE_F]
    const int tid = threadIdx.x;
    const int lane = tid & 31, wid = tid >> 5;
    const int g = lane >> 2;       // group id 0..7
    const int tg = lane & 3;       // thread in group 0..3
    const int warp_m = (wid & 1) * 64;
    const int warp_n = (wid >> 1) * 32;
    const int m0 = blockIdx.x * 128;

    int n0;
    const float* Ap;
    const float* Bp;
    float* op;
    if (MODE == 0) {
        const int sel = blockIdx.y >> 3;
        n0 = (blockIdx.y & 7) * 128;
        Ap = Amat;
        Bp = g_Wt + (size_t)sel * CC * CC;
        op = (sel == 0) ? g_q : (sel == 1 ? g_k : g_v);
    } else {
        n0 = blockIdx.y * 128;
        Ap = g_att;
        Bp = Bmat;
        op = outp;
    }

    float acc[4][4][4];
#pragma unroll
    for (int im = 0; im < 4; im++)
#pragma unroll
        for (int in = 0; in < 4; in++)
#pragma unroll
            for (int c = 0; c < 4; c++) acc[im][in][c] = 0.0f;

    // loader mapping: idx = tid + j*256; r = idx>>3 (0..127), c4 = (idx&7)*4
    float4 pa[4], pb[4];

    // ---- prologue: load stage 0 ----
#pragma unroll
    for (int j = 0; j < 4; j++) {
        int idx = tid + j * 256;
        int r = idx >> 3, c4 = (idx & 7) << 2;
        pa[j] = *reinterpret_cast<const float4*>(&Ap[(size_t)(m0 + r) * CC + c4]);
        pb[j] = *reinterpret_cast<const float4*>(&Bp[(size_t)(n0 + r) * CC + c4]);
    }
    {
        float* sA = smem;            // buf0 A
        float* sB = smem + TILE_F;   // buf0 B
#pragma unroll
        for (int j = 0; j < 4; j++) {
            int idx = tid + j * 256;
            int r = idx >> 3, c4 = (idx & 7) << 2;
            float4 v = pa[j];
            sA[r * ASTR + c4 + 0] = to_tf32(v.x); sA[r * ASTR + c4 + 1] = to_tf32(v.y);
            sA[r * ASTR + c4 + 2] = to_tf32(v.z); sA[r * ASTR + c4 + 3] = to_tf32(v.w);
            float4 w = pb[j];
            sB[r * ASTR + c4 + 0] = to_tf32(w.x); sB[r * ASTR + c4 + 1] = to_tf32(w.y);
            sB[r * ASTR + c4 + 2] = to_tf32(w.z); sB[r * ASTR + c4 + 3] = to_tf32(w.w);
        }
    }
    __syncthreads();

    for (int s = 0; s < NSTAGE; s++) {
        // prefetch next stage into registers
        if (s + 1 < NSTAGE) {
            const int k0 = (s + 1) * KT;
#pragma unroll
            for (int j = 0; j < 4; j++) {
                int idx = tid + j * 256;
                int r = idx >> 3, c4 = (idx & 7) << 2;
                pa[j] = *reinterpret_cast<const float4*>(&Ap[(size_t)(m0 + r) * CC + k0 + c4]);
                pb[j] = *reinterpret_cast<const float4*>(&Bp[(size_t)(n0 + r) * CC + k0 + c4]);
            }
        }

        // compute from buf s&1
        const float* sA = smem + (s & 1) * 2 * TILE_F;
        const float* sB = sA + TILE_F;
#pragma unroll
        for (int k8 = 0; k8 < 4; k8++) {
            const int kk = k8 * 8 + tg;
            uint32_t bf[4][2];
#pragma unroll
            for (int in = 0; in < 4; in++) {
                int n = warp_n + in * 8 + g;
                bf[in][0] = __float_as_uint(sB[n * ASTR + kk]);
                bf[in][1] = __float_as_uint(sB[n * ASTR + kk + 4]);
            }
#pragma unroll
            for (int im = 0; im < 4; im++) {
                int m = warp_m + im * 16 + g;
                uint32_t a0 = __float_as_uint(sA[m * ASTR + kk]);
                uint32_t a1 = __float_as_uint(sA[(m + 8) * ASTR + kk]);
                uint32_t a2 = __float_as_uint(sA[m * ASTR + kk + 4]);
                uint32_t a3 = __float_as_uint(sA[(m + 8) * ASTR + kk + 4]);
#pragma unroll
                for (int in = 0; in < 4; in++)
                    mma_tf32(acc[im][in], a0, a1, a2, a3, bf[in][0], bf[in][1]);
            }
        }

        if (s + 1 < NSTAGE) {
            __syncthreads();   // everyone done reading buf (s+1)&1 from stage s-1
            float* dA = smem + ((s + 1) & 1) * 2 * TILE_F;
            float* dB = dA + TILE_F;
#pragma unroll
            for (int j = 0; j < 4; j++) {
                int idx = tid + j * 256;
                int r = idx >> 3, c4 = (idx & 7) << 2;
                float4 v = pa[j];
                dA[r * ASTR + c4 + 0] = to_tf32(v.x); dA[r * ASTR + c4 + 1] = to_tf32(v.y);
                dA[r * ASTR + c4 + 2] = to_tf32(v.z); dA[r * ASTR + c4 + 3] = to_tf32(v.w);
                float4 w = pb[j];
                dB[r * ASTR + c4 + 0] = to_tf32(w.x); dB[r * ASTR + c4 + 1] = to_tf32(w.y);
                dB[r * ASTR + c4 + 2] = to_tf32(w.z); dB[r * ASTR + c4 + 3] = to_tf32(w.w);
            }
            __syncthreads();
        }
    }

    // ---- epilogue ----
#pragma unroll
    for (int im = 0; im < 4; im++) {
#pragma unroll
        for (int in = 0; in < 4; in++) {
            int row0 = m0 + warp_m + im * 16 + g;
            int col = n0 + warp_n + in * 8 + tg * 2;
            if (MODE == 0) {
                int head = col >> 6, d = col & 63;
#pragma unroll
                for (int h = 0; h < 2; h++) {
                    int m = row0 + h * 8;
                    int b = m >> 11, t = m & 2047;
                    float2 v = make_float2(acc[im][in][h * 2], acc[im][in][h * 2 + 1]);
                    *reinterpret_cast<float2*>(
                        &op[((size_t)(b * HH + head) * TT + t) * DHH + d]) = v;
                }
            } else {
                float b0 = bias[col], b1 = bias[col + 1];
#pragma unroll
                for (int h = 0; h < 2; h++) {
                    int m = row0 + h * 8;
                    float2 v = make_float2(acc[im][in][h * 2] + b0, acc[im][in][h * 2 + 1] + b1);
                    *reinterpret_cast<float2*>(&op[(size_t)m * CC + col]) = v;
                }
            }
        }
    }
}

// ============================================================
// Kernel 2: causal flash attention, fp32 SIMT (verified R2)
// ============================================================
#define ATTN_SMEM (3 * 64 * 64 * 4 + 64 * 64 * 8)

__global__ void __launch_bounds__(256) attn_kernel()
{
    extern __shared__ __align__(16) char smem_raw[];
    float* qs = reinterpret_cast<float*>(smem_raw);
    float* ks = qs + 64 * 64;
    float* vs = ks + 64 * 64;
    unsigned long long* ps2 = reinterpret_cast<unsigned long long*>(vs + 64 * 64);

    const int tid = threadIdx.x;
    const int tx = tid & 15;
    const int ty = tid >> 4;
    const int qt = blockIdx.x;
    const int bh = blockIdx.y;
    const size_t base = (size_t)bh * TT * DHH;

    for (int idx = tid; idx < 64 * 16; idx += 256) {
        int r = idx >> 4, d4 = (idx & 15) << 2;
        float4 qv = *reinterpret_cast<const float4*>(&g_q[base + (size_t)(qt * 64 + r) * DHH + d4]);
        qv.x *= 0.125f; qv.y *= 0.125f; qv.z *= 0.125f; qv.w *= 0.125f;
        *reinterpret_cast<float4*>(&qs[r * 64 + d4]) = qv;
    }

    unsigned long long o2[4][2];
    float mrow[4], lrow[4];
#pragma unroll
    for (int i = 0; i < 4; i++) {
        o2[i][0] = 0ull; o2[i][1] = 0ull;
        mrow[i] = -1e30f; lrow[i] = 0.0f;
    }

    for (int kt = 0; kt <= qt; kt++) {
        __syncthreads();
        for (int idx = tid; idx < 64 * 16; idx += 256) {
            int r = idx >> 4, d4 = idx & 15;
            float4 kv = *reinterpret_cast<const float4*>(
                &g_k[base + (size_t)(kt * 64 + r) * DHH + (d4 << 2)]);
            int sd4 = d4 ^ ((r >> 2) & 7);
            *reinterpret_cast<float4*>(&ks[r * 64 + (sd4 << 2)]) = kv;
            float4 vv = *reinterpret_cast<const float4*>(
                &g_v[base + (size_t)(kt * 64 + r) * DHH + (d4 << 2)]);
            *reinterpret_cast<float4*>(&vs[r * 64 + (d4 << 2)]) = vv;
        }
        __syncthreads();

        unsigned long long s2[4][4];
#pragma unroll
        for (int i = 0; i < 4; i++)
#pragma unroll
            for (int j = 0; j < 4; j++) s2[i][j] = 0ull;

#pragma unroll 4
        for (int d4 = 0; d4 < 16; d4++) {
            unsigned long long qa[4], qb[4], ka[4], kb[4];
#pragma unroll
            for (int i = 0; i < 4; i++) {
                ulonglong2 qp = *reinterpret_cast<const ulonglong2*>(
                    &qs[(ty * 4 + i) * 64 + (d4 << 2)]);
                qa[i] = qp.x; qb[i] = qp.y;
            }
#pragma unroll
            for (int j = 0; j < 4; j++) {
                int c = tx * 4 + j;
                int sd4 = d4 ^ ((c >> 2) & 7);
                ulonglong2 kp = *reinterpret_cast<const ulonglong2*>(
                    &ks[c * 64 + (sd4 << 2)]);
                ka[j] = kp.x; kb[j] = kp.y;
            }
#pragma unroll
            for (int i = 0; i < 4; i++)
#pragma unroll
                for (int j = 0; j < 4; j++) {
                    s2[i][j] = ffma2(qa[i], ka[j], s2[i][j]);
                    s2[i][j] = ffma2(qb[i], kb[j], s2[i][j]);
                }
        }

        const bool diag = (kt == qt);
#pragma unroll
        for (int i = 0; i < 4; i++) {
            float sv[4];
            float mloc = -1e30f;
#pragma unroll
            for (int j = 0; j < 4; j++) {
                float lo, hi;
                upk2(s2[i][j], lo, hi);
                float s = lo + hi;
                if (diag && (tx * 4 + j > ty * 4 + i)) s = -1e30f;
                sv[j] = s;
                mloc = fmaxf(mloc, s);
            }
#pragma unroll
            for (int w = 1; w < 16; w <<= 1)
                mloc = fmaxf(mloc, __shfl_xor_sync(0xffffffffu, mloc, w));
            float mnew = fmaxf(mrow[i], mloc);
            float fac = __expf(mrow[i] - mnew);
            mrow[i] = mnew;
            float rsum = 0.0f;
            float pv[4];
#pragma unroll
            for (int j = 0; j < 4; j++) {
                pv[j] = __expf(sv[j] - mnew);
                rsum += pv[j];
            }
#pragma unroll
            for (int w = 1; w < 16; w <<= 1)
                rsum += __shfl_xor_sync(0xffffffffu, rsum, w);
            lrow[i] = lrow[i] * fac + rsum;
            unsigned long long f2 = pk2(fac, fac);
            o2[i][0] = fmul2(o2[i][0], f2);
            o2[i][1] = fmul2(o2[i][1], f2);
#pragma unroll
            for (int j = 0; j < 4; j++)
                ps2[(ty * 4 + i) * 64 + tx * 4 + j] = pk2(pv[j], pv[j]);
        }
        __syncthreads();

#pragma unroll 8
        for (int j = 0; j < 64; j++) {
            ulonglong2 vp = *reinterpret_cast<const ulonglong2*>(&vs[j * 64 + tx * 4]);
#pragma unroll
            for (int i = 0; i < 4; i++) {
                unsigned long long pp = ps2[(ty * 4 + i) * 64 + j];
                o2[i][0] = ffma2(pp, vp.x, o2[i][0]);
                o2[i][1] = ffma2(pp, vp.y, o2[i][1]);
            }
        }
    }

    const int bb = bh >> 4, hh = bh & 15;
#pragma unroll
    for (int i = 0; i < 4; i++) {
        float inv = 1.0f / lrow[i];
        float f0, f1, f2, f3;
        upk2(o2[i][0], f0, f1);
        upk2(o2[i][1], f2, f3);
        float4 o4 = make_float4(f0 * inv, f1 * inv, f2 * inv, f3 * inv);
        int trow = qt * 64 + ty * 4 + i;
        *reinterpret_cast<float4*>(
            &g_att[(size_t)(bb * TT + trow) * CC + hh * DHH + tx * 4]) = o4;
    }
}

// ============================================================
extern "C" void kernel_launch(void* const* d_in, const int* in_sizes, int n_in,
                              void* d_out, int out_size)
{
    const float* x  = (const float*)d_in[0];
    const float* Wq = (const float*)d_in[1];
    const float* Wk = (const float*)d_in[2];
    const float* Wv = (const float*)d_in[3];
    const float* Wo = (const float*)d_in[4];
    const float* bo = (const float*)d_in[5];
    float* out = (float*)d_out;

    cudaFuncSetAttribute(gemm_mma<0>, cudaFuncAttributeMaxDynamicSharedMemorySize, GEMM_SMEM);
    cudaFuncSetAttribute(gemm_mma<1>, cudaFuncAttributeMaxDynamicSharedMemorySize, GEMM_SMEM);
    cudaFuncSetAttribute(attn_kernel, cudaFuncAttributeMaxDynamicSharedMemorySize, ATTN_SMEM);

    wt_kernel<<<dim3(32, 32, 3), dim3(32, 8)>>>(Wq, Wk, Wv);
    gemm_mma<0><<<dim3(M_TOT / 128, 24), 256, GEMM_SMEM>>>(x, nullptr, nullptr, nullptr);
    attn_kernel<<<dim3(TT / 64, BB * HH), 256, ATTN_SMEM>>>();
    gemm_mma<1><<<dim3(M_TOT / 128, 8), 256, GEMM_SMEM>>>(nullptr, Wo, bo, out);
}

// round 6
// speedup vs baseline: 2.9283x; 1.9705x over previous
#include <cuda_runtime.h>
#include <cstdint>

#define BB 4
#define TT 2048
#define CC 1024
#define HH 16
#define DHH 64
#define M_TOT (BB*TT)   // 8192

// Scratch (static device globals — no allocation in kernel_launch)
__device__ float g_q[BB*HH*TT*DHH];
__device__ float g_k[BB*HH*TT*DHH];
__device__ float g_v[BB*HH*TT*DHH];
__device__ float g_att[BB*TT*CC];
__device__ float g_Wt[3*CC*CC];      // transposed qkv weights: [sel][n=h*64+d][k=c]

// ================= helpers =================
__device__ __forceinline__ float to_tf32(float x) {
    uint32_t u;
    asm("cvt.rna.tf32.f32 %0, %1;" : "=r"(u) : "f"(x));
    return __uint_as_float(u);
}

__device__ __forceinline__ void mma_tf32(float c[4],
                                         uint32_t a0, uint32_t a1, uint32_t a2, uint32_t a3,
                                         uint32_t b0, uint32_t b1) {
    asm volatile(
        "mma.sync.aligned.m16n8k8.row.col.f32.tf32.tf32.f32 "
        "{%0,%1,%2,%3}, {%4,%5,%6,%7}, {%8,%9}, {%0,%1,%2,%3};"
        : "+f"(c[0]), "+f"(c[1]), "+f"(c[2]), "+f"(c[3])
        : "r"(a0), "r"(a1), "r"(a2), "r"(a3), "r"(b0), "r"(b1));
}

// ============================================================
// Kernel 0: weight transpose  g_Wt[sel][n=h*64+d][k=c] = W_sel[h][c][d]
// ============================================================
__global__ void __launch_bounds__(256) wt_kernel(
    const float* __restrict__ Wq, const float* __restrict__ Wk, const float* __restrict__ Wv)
{
    __shared__ float t[32][33];
    const float* W = (blockIdx.z == 0) ? Wq : (blockIdx.z == 1 ? Wk : Wv);
    float* out = g_Wt + (size_t)blockIdx.z * CC * CC;
    const int head = blockIdx.y >> 1;
    const int d0 = (blockIdx.y & 1) * 32;
    const int k0 = blockIdx.x * 32;
    const int tx = threadIdx.x, ty = threadIdx.y;
#pragma unroll
    for (int j = 0; j < 4; j++) {
        int k = k0 + ty + j * 8;
        t[ty + j * 8][tx] = W[((size_t)head * CC + k) * DHH + d0 + tx];
    }
    __syncthreads();
#pragma unroll
    for (int j = 0; j < 4; j++) {
        int n = head * 64 + d0 + ty + j * 8;
        out[(size_t)n * CC + k0 + tx] = t[tx][ty + j * 8];
    }
}

// ============================================================
// mma.sync tf32 GEMM, 128x128 CTA tile, 8 warps (2x4), warp tile 64x32.
// MODE 0: qkv   MODE 1: proj (+bias)
// ============================================================
#define KT 32
#define NSTAGE (CC / KT)        // 32
#define ASTR 36
#define TILE_F (128 * ASTR)
#define GEMM_SMEM (2 * 2 * TILE_F * 4)

template <int MODE>
__global__ void __launch_bounds__(256) gemm_mma(
    const float* __restrict__ Amat, const float* __restrict__ Bmat,
    const float* __restrict__ bias, float* __restrict__ outp)
{
    extern __shared__ __align__(16) float smem[];
    const int tid = threadIdx.x;
    const int lane = tid & 31, wid = tid >> 5;
    const int g = lane >> 2;
    const int tg = lane & 3;
    const int warp_m = (wid & 1) * 64;
    const int warp_n = (wid >> 1) * 32;
    const int m0 = blockIdx.x * 128;

    int n0;
    const float* Ap;
    const float* Bp;
    float* op;
    if (MODE == 0) {
        const int sel = blockIdx.y >> 3;
        n0 = (blockIdx.y & 7) * 128;
        Ap = Amat;
        Bp = g_Wt + (size_t)sel * CC * CC;
        op = (sel == 0) ? g_q : (sel == 1 ? g_k : g_v);
    } else {
        n0 = blockIdx.y * 128;
        Ap = g_att;
        Bp = Bmat;
        op = outp;
    }

    float acc[4][4][4];
#pragma unroll
    for (int im = 0; im < 4; im++)
#pragma unroll
        for (int in = 0; in < 4; in++)
#pragma unroll
            for (int c = 0; c < 4; c++) acc[im][in][c] = 0.0f;

    float4 pa[4], pb[4];
#pragma unroll
    for (int j = 0; j < 4; j++) {
        int idx = tid + j * 256;
        int r = idx >> 3, c4 = (idx & 7) << 2;
        pa[j] = *reinterpret_cast<const float4*>(&Ap[(size_t)(m0 + r) * CC + c4]);
        pb[j] = *reinterpret_cast<const float4*>(&Bp[(size_t)(n0 + r) * CC + c4]);
    }
    {
        float* sA = smem;
        float* sB = smem + TILE_F;
#pragma unroll
        for (int j = 0; j < 4; j++) {
            int idx = tid + j * 256;
            int r = idx >> 3, c4 = (idx & 7) << 2;
            float4 v = pa[j];
            sA[r * ASTR + c4 + 0] = to_tf32(v.x); sA[r * ASTR + c4 + 1] = to_tf32(v.y);
            sA[r * ASTR + c4 + 2] = to_tf32(v.z); sA[r * ASTR + c4 + 3] = to_tf32(v.w);
            float4 w = pb[j];
            sB[r * ASTR + c4 + 0] = to_tf32(w.x); sB[r * ASTR + c4 + 1] = to_tf32(w.y);
            sB[r * ASTR + c4 + 2] = to_tf32(w.z); sB[r * ASTR + c4 + 3] = to_tf32(w.w);
        }
    }
    __syncthreads();

    for (int s = 0; s < NSTAGE; s++) {
        if (s + 1 < NSTAGE) {
            const int k0 = (s + 1) * KT;
#pragma unroll
            for (int j = 0; j < 4; j++) {
                int idx = tid + j * 256;
                int r = idx >> 3, c4 = (idx & 7) << 2;
                pa[j] = *reinterpret_cast<const float4*>(&Ap[(size_t)(m0 + r) * CC + k0 + c4]);
                pb[j] = *reinterpret_cast<const float4*>(&Bp[(size_t)(n0 + r) * CC + k0 + c4]);
            }
        }

        const float* sA = smem + (s & 1) * 2 * TILE_F;
        const float* sB = sA + TILE_F;
#pragma unroll
        for (int k8 = 0; k8 < 4; k8++) {
            const int kk = k8 * 8 + tg;
            uint32_t bf[4][2];
#pragma unroll
            for (int in = 0; in < 4; in++) {
                int n = warp_n + in * 8 + g;
                bf[in][0] = __float_as_uint(sB[n * ASTR + kk]);
                bf[in][1] = __float_as_uint(sB[n * ASTR + kk + 4]);
            }
#pragma unroll
            for (int im = 0; im < 4; im++) {
                int m = warp_m + im * 16 + g;
                uint32_t a0 = __float_as_uint(sA[m * ASTR + kk]);
                uint32_t a1 = __float_as_uint(sA[(m + 8) * ASTR + kk]);
                uint32_t a2 = __float_as_uint(sA[m * ASTR + kk + 4]);
                uint32_t a3 = __float_as_uint(sA[(m + 8) * ASTR + kk + 4]);
#pragma unroll
                for (int in = 0; in < 4; in++)
                    mma_tf32(acc[im][in], a0, a1, a2, a3, bf[in][0], bf[in][1]);
            }
        }

        if (s + 1 < NSTAGE) {
            __syncthreads();
            float* dA = smem + ((s + 1) & 1) * 2 * TILE_F;
            float* dB = dA + TILE_F;
#pragma unroll
            for (int j = 0; j < 4; j++) {
                int idx = tid + j * 256;
                int r = idx >> 3, c4 = (idx & 7) << 2;
                float4 v = pa[j];
                dA[r * ASTR + c4 + 0] = to_tf32(v.x); dA[r * ASTR + c4 + 1] = to_tf32(v.y);
                dA[r * ASTR + c4 + 2] = to_tf32(v.z); dA[r * ASTR + c4 + 3] = to_tf32(v.w);
                float4 w = pb[j];
                dB[r * ASTR + c4 + 0] = to_tf32(w.x); dB[r * ASTR + c4 + 1] = to_tf32(w.y);
                dB[r * ASTR + c4 + 2] = to_tf32(w.z); dB[r * ASTR + c4 + 3] = to_tf32(w.w);
            }
            __syncthreads();
        }
    }

#pragma unroll
    for (int im = 0; im < 4; im++) {
#pragma unroll
        for (int in = 0; in < 4; in++) {
            int row0 = m0 + warp_m + im * 16 + g;
            int col = n0 + warp_n + in * 8 + tg * 2;
            if (MODE == 0) {
                int head = col >> 6, d = col & 63;
#pragma unroll
                for (int h = 0; h < 2; h++) {
                    int m = row0 + h * 8;
                    int b = m >> 11, t = m & 2047;
                    float2 v = make_float2(acc[im][in][h * 2], acc[im][in][h * 2 + 1]);
                    *reinterpret_cast<float2*>(
                        &op[((size_t)(b * HH + head) * TT + t) * DHH + d]) = v;
                }
            } else {
                float b0 = bias[col], b1 = bias[col + 1];
#pragma unroll
                for (int h = 0; h < 2; h++) {
                    int m = row0 + h * 8;
                    float2 v = make_float2(acc[im][in][h * 2] + b0, acc[im][in][h * 2 + 1] + b1);
                    *reinterpret_cast<float2*>(&op[(size_t)m * CC + col]) = v;
                }
            }
        }
    }
}

// ============================================================
// Kernel 2: causal flash attention on mma.sync tf32.
// BR=BC=64, 4 warps, each warp owns 16 q-rows (full row -> quad-local softmax).
// Smem strides: qs/ks/ps 68 (frag pattern 4g+tg conflict-free),
//               vs 72 (PV B-frag pattern 8tg+8in+g conflict-free).
// ============================================================
#define QS_STR 68
#define VS_STR 72
#define ATTN_SMEM ((3 * 64 * QS_STR + 64 * VS_STR) * 4)   // 70656 B

__global__ void __launch_bounds__(128) attn_kernel()
{
    extern __shared__ __align__(16) float sm[];
    float* qs = sm;                        // [64][68] tf32, pre-scaled
    float* ks = qs + 64 * QS_STR;          // [64][68] tf32
    float* ps = ks + 64 * QS_STR;          // [64][68] tf32
    float* vs = ps + 64 * QS_STR;          // [64][72] tf32

    const int tid = threadIdx.x;
    const int lane = tid & 31, w = tid >> 5;
    const int g = lane >> 2, tg = lane & 3;
    const int qt = blockIdx.x, bh = blockIdx.y;
    const size_t base = (size_t)bh * TT * DHH;

    const int rA = w * 16 + g;       // local q-row A
    const int rB = rA + 8;           // local q-row B

    // ---- load Q tile (scale folded, tf32) ----
#pragma unroll
    for (int i = 0; i < 8; i++) {
        int idx = tid + i * 128;
        int r = idx >> 4, c4 = (idx & 15) << 2;
        float4 v = *reinterpret_cast<const float4*>(
            &g_q[base + (size_t)(qt * 64 + r) * DHH + c4]);
        v.x = to_tf32(v.x * 0.125f); v.y = to_tf32(v.y * 0.125f);
        v.z = to_tf32(v.z * 0.125f); v.w = to_tf32(v.w * 0.125f);
        *reinterpret_cast<float4*>(&qs[r * QS_STR + c4]) = v;
    }

    float oacc[8][4];
#pragma unroll
    for (int in = 0; in < 8; in++)
#pragma unroll
        for (int c = 0; c < 4; c++) oacc[in][c] = 0.0f;
    float mA = -1e30f, mB = -1e30f, lA = 0.0f, lB = 0.0f;

    for (int kt = 0; kt <= qt; kt++) {
        __syncthreads();   // previous PV reads of vs / ps done
        // ---- load K, V tiles ----
#pragma unroll
        for (int i = 0; i < 8; i++) {
            int idx = tid + i * 128;
            int r = idx >> 4, c4 = (idx & 15) << 2;
            float4 kv = *reinterpret_cast<const float4*>(
                &g_k[base + (size_t)(kt * 64 + r) * DHH + c4]);
            kv.x = to_tf32(kv.x); kv.y = to_tf32(kv.y);
            kv.z = to_tf32(kv.z); kv.w = to_tf32(kv.w);
            *reinterpret_cast<float4*>(&ks[r * QS_STR + c4]) = kv;
            float4 vv = *reinterpret_cast<const float4*>(
                &g_v[base + (size_t)(kt * 64 + r) * DHH + c4]);
            vv.x = to_tf32(vv.x); vv.y = to_tf32(vv.y);
            vv.z = to_tf32(vv.z); vv.w = to_tf32(vv.w);
            *reinterpret_cast<float4*>(&vs[r * VS_STR + c4]) = vv;
        }
        __syncthreads();

        // ---- S = Q K^T ----
        float sacc[8][4];
#pragma unroll
        for (int in = 0; in < 8; in++)
#pragma unroll
            for (int c = 0; c < 4; c++) sacc[in][c] = 0.0f;

#pragma unroll
        for (int k8 = 0; k8 < 8; k8++) {
            const int kk = k8 * 8 + tg;
            uint32_t a0 = __float_as_uint(qs[rA * QS_STR + kk]);
            uint32_t a1 = __float_as_uint(qs[rB * QS_STR + kk]);
            uint32_t a2 = __float_as_uint(qs[rA * QS_STR + kk + 4]);
            uint32_t a3 = __float_as_uint(qs[rB * QS_STR + kk + 4]);
#pragma unroll
            for (int in = 0; in < 8; in++) {
                uint32_t b0 = __float_as_uint(ks[(in * 8 + g) * QS_STR + kk]);
                uint32_t b1 = __float_as_uint(ks[(in * 8 + g) * QS_STR + kk + 4]);
                mma_tf32(sacc[in], a0, a1, a2, a3, b0, b1);
            }
        }

        // ---- causal mask (diag tile only) ----
        if (kt == qt) {
#pragma unroll
            for (int in = 0; in < 8; in++) {
                int c0 = in * 8 + tg * 2;
                if (c0 > rA)     sacc[in][0] = -1e30f;
                if (c0 + 1 > rA) sacc[in][1] = -1e30f;
                if (c0 > rB)     sacc[in][2] = -1e30f;
                if (c0 + 1 > rB) sacc[in][3] = -1e30f;
            }
        }

        // ---- online softmax (quad-local reductions) ----
        float mlA = -1e30f, mlB = -1e30f;
#pragma unroll
        for (int in = 0; in < 8; in++) {
            mlA = fmaxf(mlA, fmaxf(sacc[in][0], sacc[in][1]));
            mlB = fmaxf(mlB, fmaxf(sacc[in][2], sacc[in][3]));
        }
#pragma unroll
        for (int msk = 1; msk < 4; msk <<= 1) {
            mlA = fmaxf(mlA, __shfl_xor_sync(0xffffffffu, mlA, msk));
            mlB = fmaxf(mlB, __shfl_xor_sync(0xffffffffu, mlB, msk));
        }
        float mnA = fmaxf(mA, mlA), mnB = fmaxf(mB, mlB);
        float facA = __expf(mA - mnA), facB = __expf(mB - mnB);
        mA = mnA; mB = mnB;

        float rsA = 0.0f, rsB = 0.0f;
#pragma unroll
        for (int in = 0; in < 8; in++) {
            float p0 = __expf(sacc[in][0] - mnA);
            float p1 = __expf(sacc[in][1] - mnA);
            float p2 = __expf(sacc[in][2] - mnB);
            float p3 = __expf(sacc[in][3] - mnB);
            rsA += p0 + p1; rsB += p2 + p3;
            int col = in * 8 + tg * 2;
            *reinterpret_cast<float2*>(&ps[rA * QS_STR + col]) =
                make_float2(to_tf32(p0), to_tf32(p1));
            *reinterpret_cast<float2*>(&ps[rB * QS_STR + col]) =
                make_float2(to_tf32(p2), to_tf32(p3));
        }
#pragma unroll
        for (int msk = 1; msk < 4; msk <<= 1) {
            rsA += __shfl_xor_sync(0xffffffffu, rsA, msk);
            rsB += __shfl_xor_sync(0xffffffffu, rsB, msk);
        }
        lA = lA * facA + rsA;
        lB = lB * facB + rsB;
#pragma unroll
        for (int in = 0; in < 8; in++) {
            oacc[in][0] *= facA; oacc[in][1] *= facA;
            oacc[in][2] *= facB; oacc[in][3] *= facB;
        }
        __syncthreads();   // ps visible to whole warp's quads

        // ---- O += P V ----
#pragma unroll
        for (int k8 = 0; k8 < 8; k8++) {
            const int kk = k8 * 8 + tg;
            uint32_t a0 = __float_as_uint(ps[rA * QS_STR + kk]);
            uint32_t a1 = __float_as_uint(ps[rB * QS_STR + kk]);
            uint32_t a2 = __float_as_uint(ps[rA * QS_STR + kk + 4]);
            uint32_t a3 = __float_as_uint(ps[rB * QS_STR + kk + 4]);
#pragma unroll
            for (int in = 0; in < 8; in++) {
                uint32_t b0 = __float_as_uint(vs[kk * VS_STR + in * 8 + g]);
                uint32_t b1 = __float_as_uint(vs[(kk + 4) * VS_STR + in * 8 + g]);
                mma_tf32(oacc[in], a0, a1, a2, a3, b0, b1);
            }
        }
    }

    // ---- epilogue ----
    const float invA = 1.0f / lA, invB = 1.0f / lB;
    const int bb = bh >> 4, hh = bh & 15;
    const int rowA = qt * 64 + rA;
#pragma unroll
    for (int in = 0; in < 8; in++) {
        int col = hh * 64 + in * 8 + tg * 2;
        *reinterpret_cast<float2*>(&g_att[(size_t)(bb * TT + rowA) * CC + col]) =
            make_float2(oacc[in][0] * invA, oacc[in][1] * invA);
        *reinterpret_cast<float2*>(&g_att[(size_t)(bb * TT + rowA + 8) * CC + col]) =
            make_float2(oacc[in][2] * invB, oacc[in][3] * invB);
    }
}

// ============================================================
extern "C" void kernel_launch(void* const* d_in, const int* in_sizes, int n_in,
                              void* d_out, int out_size)
{
    const float* x  = (const float*)d_in[0];
    const float* Wq = (const float*)d_in[1];
    const float* Wk = (const float*)d_in[2];
    const float* Wv = (const float*)d_in[3];
    const float* Wo = (const float*)d_in[4];
    const float* bo = (const float*)d_in[5];
    float* out = (float*)d_out;

    cudaFuncSetAttribute(gemm_mma<0>, cudaFuncAttributeMaxDynamicSharedMemorySize, GEMM_SMEM);
    cudaFuncSetAttribute(gemm_mma<1>, cudaFuncAttributeMaxDynamicSharedMemorySize, GEMM_SMEM);
    cudaFuncSetAttribute(attn_kernel, cudaFuncAttributeMaxDynamicSharedMemorySize, ATTN_SMEM);

    wt_kernel<<<dim3(32, 32, 3), dim3(32, 8)>>>(Wq, Wk, Wv);
    gemm_mma<0><<<dim3(M_TOT / 128, 24), 256, GEMM_SMEM>>>(x, nullptr, nullptr, nullptr);
    attn_kernel<<<dim3(TT / 64, BB * HH), 128, ATTN_SMEM>>>();
    gemm_mma<1><<<dim3(M_TOT / 128, 8), 256, GEMM_SMEM>>>(nullptr, Wo, bo, out);
}